// round 17
// baseline (speedup 1.0000x reference)
#include <cuda_runtime.h>

#define NG 21
#define NTRIP 69
#define NTILE 138

typedef unsigned long long ull;

struct Meta {
    const float* f[6];
    const float* w[6];
    float*       out;
    int cg_off[NG][6];
    int col_base[NG][6];
    int trip_l1[NTRIP];
    int trip_l2[NTRIP];
    int trip_l[NTRIP];
    int trip_off[NTRIP];
};

__device__ float d_cg[4096];
__device__ float d_wt[565248];   // planar weights: [0,282624) real, [282624,565248) imag

#define WPLANE 282624
#define NCG 4066

__constant__ int c_NUMCOLS[6] = {1536, 2560, 3328, 3584, 3584, 3072};
__constant__ int c_FOFF[7]    = {0, 32, 128, 288, 512, 800, 1152};
__constant__ int c_OUTOFF[6]  = {0, 8192, 32768, 73728, 131072, 204800};
__constant__ int c_WTP[7] = {0, 24576, 65536, 118784, 176128, 233472, 282624};
__constant__ int c_TCUM[7] = {0, 12, 32, 58, 86, 114, 138};

__constant__ double c_fact[17] = {
    1.0, 1.0, 2.0, 6.0, 24.0, 120.0, 720.0, 5040.0, 40320.0, 362880.0,
    3628800.0, 39916800.0, 479001600.0, 6227020800.0, 87178291200.0,
    1307674368000.0, 20922789888000.0
};

// ---- packed f32x2 helpers -------------------------------------------------
__device__ __forceinline__ ull ffma2(ull a, ull b, ull c) {
    ull d; asm("fma.rn.f32x2 %0, %1, %2, %3;" : "=l"(d) : "l"(a), "l"(b), "l"(c)); return d;
}
__device__ __forceinline__ float2 upk(ull a) {
    float2 r; asm("mov.b64 {%0,%1}, %2;" : "=f"(r.x), "=f"(r.y) : "l"(a)); return r;
}
#define SGN2 0x8000000080000000ULL

// ---------------------------------------------------------------------------
// Setup kernel: CG coefficients + smem-tiled planar weight transpose
// ---------------------------------------------------------------------------
__device__ double cg_coeff_d(int l1, int l2, int l, int m1, int m2, int m) {
    double pref = sqrt((2.0 * l + 1.0) * c_fact[l + l1 - l2] * c_fact[l - l1 + l2] *
                       c_fact[l1 + l2 - l] / c_fact[l1 + l2 + l + 1]);
    pref *= sqrt(c_fact[l + m] * c_fact[l - m] * c_fact[l1 - m1] * c_fact[l1 + m1] *
                 c_fact[l2 - m2] * c_fact[l2 + m2]);
    int kmin = 0;
    if (l2 - l - m1 > kmin) kmin = l2 - l - m1;
    if (l1 + m2 - l > kmin) kmin = l1 + m2 - l;
    int kmax = l1 + l2 - l;
    if (l1 - m1 < kmax) kmax = l1 - m1;
    if (l2 + m2 < kmax) kmax = l2 + m2;
    double s = 0.0;
    for (int k = kmin; k <= kmax; k++) {
        double d = c_fact[k] * c_fact[l1 + l2 - l - k] * c_fact[l1 - m1 - k] *
                   c_fact[l2 + m2 - k] * c_fact[l - l2 + m1 + k] * c_fact[l - l1 - m2 + k];
        s += ((k & 1) ? -1.0 : 1.0) / d;
    }
    return pref * s;
}

__global__ void setup_kernel(Meta meta) {
    if (blockIdx.x < NTRIP) {
        int tr = blockIdx.x;
        int l1 = meta.trip_l1[tr], l2 = meta.trip_l2[tr], l = meta.trip_l[tr];
        int off = meta.trip_off[tr];
        int n1 = 2 * l1 + 1, n2 = 2 * l2 + 1;
        int idx = threadIdx.x;
        if (idx >= n1 * n2) return;
        int m1i = idx / n2, m2i = idx % n2;
        int m1 = m1i - l1, m2 = m2i - l2, m = m1 + m2;
        float c = 0.0f;
        if (m >= -l && m <= l)
            c = (float)cg_coeff_d(l1, l2, l, m1, m2, m);
        d_cg[off + idx] = c;
        return;
    }
    __shared__ float ts[4096];
    int tile = blockIdx.x - NTRIP;
    int l = 0;
#pragma unroll
    for (int ll = 1; ll < 6; ll++)
        if (tile >= c_TCUM[ll]) l = ll;
    int c0 = (tile - c_TCUM[l]) * 128;
    int ncols = c_NUMCOLS[l];
    const float* wsrc = meta.w[l];
    int tid = threadIdx.x;
#pragma unroll
    for (int k = 0; k < 16; k++) {
        int idx = tid + k * 256;
        int t = idx >> 8;
        int low = idx & 255;
        ts[idx] = wsrc[t * ncols * 2 + c0 * 2 + low];
    }
    __syncthreads();
    int dbase = c_WTP[l] + (c0 >> 2) * 64;
#pragma unroll
    for (int k = 0; k < 16; k++) {
        int idx = tid + k * 256;
        int plane = idx >> 11;
        int r = idx & 2047;
        int c4l = r >> 6;
        int rem = r & 63;
        int t = rem >> 2;
        int j3 = rem & 3;
        d_wt[plane * WPLANE + dbase + c4l * 64 + t * 4 + j3] =
            ts[t * 256 + (c4l * 4 + j3) * 2 + plane];
    }
}

// ---------------------------------------------------------------------------
// Stage-2 inner accumulation (R14 champion configuration)
// ---------------------------------------------------------------------------
template <int CNT>
__device__ __forceinline__ void s2_acc(const ulonglong2* __restrict__ wr,
                                       const ulonglong2* __restrict__ wi,
                                       const ulonglong2* __restrict__ fr,
                                       const ulonglong2* __restrict__ fi,
                                       int len, int ooff, float* out_s)
{
    ull A[CNT], C[CNT];
#pragma unroll
    for (int q = 0; q < CNT; q++) { A[q] = 0; C[q] = 0; }
#pragma unroll 4
    for (int p = 0; p < len; p++) {
        ulonglong2 w_r = wr[p * 16];
        ulonglong2 w_i = wi[p * 16];
        ull wnx = w_i.x ^ SGN2;
        ull wny = w_i.y ^ SGN2;
#pragma unroll
        for (int q = 0; q < CNT; q++) {
            ulonglong2 f_r = fr[q * 64 + p];
            ulonglong2 f_i = fi[q * 64 + p];
            A[q] = ffma2(w_r.x, f_r.x, A[q]);
            A[q] = ffma2(w_r.y, f_r.y, A[q]);
            A[q] = ffma2(wnx,   f_i.x, A[q]);
            A[q] = ffma2(wny,   f_i.y, A[q]);
            C[q] = ffma2(w_r.x, f_i.x, C[q]);
            C[q] = ffma2(w_r.y, f_i.y, C[q]);
            C[q] = ffma2(w_i.x, f_r.x, C[q]);
            C[q] = ffma2(w_i.y, f_r.y, C[q]);
        }
    }
#pragma unroll
    for (int q = 0; q < CNT; q++) {
        float2 a2 = upk(A[q]), c2 = upk(C[q]);
        atomicAdd(&out_s[ooff + 2 * q],     a2.x + a2.y);
        atomicAdd(&out_s[ooff + 2 * q + 1], c2.x + c2.y);
    }
}

// ---------------------------------------------------------------------------
// Stage-2 with in-thread entry decode, cnt-sorted enumeration
// ---------------------------------------------------------------------------
__device__ __noinline__ void stage2(int E, int LA, int LB, int lcs,
                                    const int* colbase6,
                                    const float* frag_r, const float* frag_i,
                                    float* out_s, int tid)
{
    int csplit = 1 << lcs;
    int cmask = csplit - 1;
    int len = 64 >> lcs;
    int N4 = 0, N3 = 0;
    for (int l = LA; l <= LB; l++) { N4 += l >> 1; N3 += (l & 1); }
    int U4e = N4 * csplit, U3e = N3 * csplit;
    int LA2 = LA * LA;
    for (int e = tid; e < E; e += 256) {
        int t = e & 15;
        int u = e >> 4;
        int l, k0, cnt, ch;
        if (u < U4e) {
            int q = u >> lcs; ch = u & cmask;
            l = LA;
            while (q >= (l >> 1)) { q -= (l >> 1); l++; }
            k0 = q * 4; cnt = 4;
        } else if (u < U4e + U3e) {
            int idx = u - U4e;
            int j = idx >> lcs; ch = idx & cmask;
            l = (LA & 1) ? LA : LA + 1;
            l += 2 * j;
            k0 = (l >> 1) * 4; cnt = 3;
        } else {
            int idx = u - U4e - U3e;
            int j = idx >> lcs; ch = idx & cmask;
            l = (LA & 1) ? LA + 1 : LA;
            l += 2 * j;
            k0 = (l >> 1) * 4; cnt = 1;
        }
        int pstart = ch * len;
        int woff = c_WTP[l] + ((colbase6[l] >> 2) + pstart) * 64 + t * 4;
        int kk0 = (l * l - LA2) + k0;
        int ooff = c_FOFF[l] + (t * (2 * l + 1) + k0) * 2;
        const ulonglong2* wr = (const ulonglong2*)(d_wt + woff);
        const ulonglong2* wi = (const ulonglong2*)(d_wt + WPLANE + woff);
        const ulonglong2* fr = (const ulonglong2*)frag_r + kk0 * 64 + pstart;
        const ulonglong2* fi = (const ulonglong2*)frag_i + kk0 * 64 + pstart;
        if (cnt == 4)      s2_acc<4>(wr, wi, fr, fi, len, ooff, out_s);
        else if (cnt == 3) s2_acc<3>(wr, wi, fr, fi, len, ooff, out_s);
        else               s2_acc<1>(wr, wi, fr, fi, len, ooff, out_s);
    }
}

// ---- constexpr helpers -----------------------------------------------------
__host__ __device__ constexpr int KQf(int LA, int LB) {
    int s = 0;
    for (int l = LA; l <= LB; l++) s += (l + 2) / 2;
    return s;
}
__host__ __device__ constexpr int LCSf(int E0) {
    return (E0 >= 256) ? 0 : ((E0 >= 128) ? 1 : ((E0 >= 64) ? 2 : ((E0 >= 32) ? 3 : 4)));
}

// ---------------------------------------------------------------------------
// Stage-1 helper (unchanged body)
// ---------------------------------------------------------------------------
template <int L1, int L2, int LA, int LB>
__device__ __forceinline__ void stage1(
    int g, const Meta& meta, const float* __restrict__ f_s,
    const float* __restrict__ cg_a,
    float* __restrict__ frag_r, float* __restrict__ frag_i, int tid)
{
    constexpr int N1 = 2 * L1 + 1;
    constexpr int N2 = 2 * L2 + 1;
    constexpr int STRIDE = N1 * N2;
    constexpr int SK = (LB + 1) * (LB + 1) - LA * LA;
    int i = tid >> 4, j = tid & 15;
    float accr[SK], acci[SK];
#pragma unroll
    for (int q = 0; q < SK; q++) { accr[q] = 0.0f; acci[q] = 0.0f; }
    const float* cgsub = cg_a + meta.cg_off[g][LA];
    const float* f1 = f_s + c_FOFF[L1] + i * N1 * 2;
    const float* f2 = f_s + c_FOFF[L2] + j * N2 * 2;
#pragma unroll
    for (int m1 = 0; m1 < N1; m1++) {
        float ar = f1[2 * m1], ai = f1[2 * m1 + 1];
#pragma unroll
        for (int m2 = 0; m2 < N2; m2++) {
            float br = f2[2 * m2], bi = f2[2 * m2 + 1];
            float pr = ar * br - ai * bi;
            float pi = ar * bi + ai * br;
            int m = m1 + m2 - L1 - L2;
#pragma unroll
            for (int l = LA; l <= LB; l++) {
                if (m >= -l && m <= l) {
                    float c = cgsub[(l - LA) * STRIDE + m1 * N2 + m2];
                    int kk = (l * l - LA * LA) + m + l;
                    accr[kk] += c * pr;
                    acci[kk] += c * pi;
                }
            }
        }
    }
#pragma unroll
    for (int q = 0; q < SK; q++) {
        frag_r[q * 256 + tid] = accr[q];
        frag_i[q * 256 + tid] = acci[q];
    }
}

// ---------------------------------------------------------------------------
// Fused phase pair: s1(a); s1(b); bar; s2(a); s2(b)  — halves barrier count
// and averages stage-2 imbalance across the two subranges.
// ---------------------------------------------------------------------------
template <int L1a, int L2a, int LAa, int LBa,
          int L1b, int L2b, int LAb, int LBb>
__device__ __forceinline__ void process_pair(
    int ga, int gb, const Meta& meta, float* __restrict__ f_s,
    float* __restrict__ out_s, const float* __restrict__ cg_a,
    float* __restrict__ frag_r, float* __restrict__ frag_i, int tid)
{
    constexpr int SKa = (LBa + 1) * (LBa + 1) - LAa * LAa;
    constexpr int SKb = (LBb + 1) * (LBb + 1) - LAb * LAb;
    static_assert(SKa + SKb <= 32, "frag capacity");
    constexpr int E0a = 16 * KQf(LAa, LBa);
    constexpr int E0b = 16 * KQf(LAb, LBb);
    constexpr int LCSa = LCSf(E0a);
    constexpr int LCSb = LCSf(E0b);

    __syncthreads();  // prior stage2 done reading frag
    stage1<L1a, L2a, LAa, LBa>(ga, meta, f_s, cg_a, frag_r, frag_i, tid);
    stage1<L1b, L2b, LAb, LBb>(gb, meta, f_s, cg_a,
                               frag_r + SKa * 256, frag_i + SKa * 256, tid);
    __syncthreads();  // fragments (both subranges) ready
    stage2(E0a << LCSa, LAa, LBa, LCSa, meta.col_base[ga], frag_r, frag_i, out_s, tid);
    stage2(E0b << LCSb, LAb, LBb, LCSb, meta.col_base[gb],
           frag_r + SKa * 256, frag_i + SKa * 256, out_s, tid);
}

__global__ void __launch_bounds__(256, 2) uf_kernel(Meta meta) {
    extern __shared__ float smem[];
    float* f_s    = smem;                 // 1152
    float* out_s  = smem + 1152;          // 1152
    float* cg_a   = smem + 2304;          // 4096 (4066 used)
    float* frag_r = smem + 6400;          // 8192 (32 rows * 256)
    float* frag_i = smem + 14592;         // 8192   total 22784 words = 91136 B

    int tid = threadIdx.x;
    int b = blockIdx.x;

#pragma unroll
    for (int l = 0; l < 6; l++) {
        int n = 32 * (2 * l + 1);
        const float* src = meta.f[l] + b * n;
        for (int s = tid; s < n; s += 256) f_s[c_FOFF[l] + s] = src[s];
    }
    for (int s = tid; s < 1152; s += 256) out_s[s] = 0.0f;
    for (int s = tid; s < NCG; s += 256) cg_a[s] = d_cg[s];

#define PP(A1, A2, GA, LAa, LBa, B1, B2, GB, LAb, LBb) \
    process_pair<A1, A2, LAa, LBa, B1, B2, LAb, LBb>(GA, GB, meta, f_s, out_s, cg_a, frag_r, frag_i, tid)
    // 16 fused phases covering all 32 subranges (SKa+SKb <= 32)
    PP(3, 1, 7,  2, 4,   4, 1, 11, 5, 5);   // 21 + 11
    PP(4, 2, 12, 2, 4,   4, 2, 12, 5, 5);   // 21 + 11
    PP(5, 3, 18, 2, 4,   5, 3, 18, 5, 5);   // 21 + 11
    PP(3, 2, 8,  4, 5,   5, 0, 15, 5, 5);   // 20 + 11
    PP(3, 3, 9,  4, 5,   5, 2, 17, 5, 5);   // 20 + 11
    PP(4, 3, 13, 4, 5,   1, 1, 2,  0, 2);   // 20 + 9
    PP(4, 4, 14, 4, 5,   2, 2, 5,  4, 4);   // 20 + 9
    PP(5, 1, 16, 4, 5,   4, 0, 10, 4, 4);   // 20 + 9
    PP(5, 4, 19, 4, 5,   3, 0, 6,  3, 3);   // 20 + 7
    PP(5, 5, 20, 4, 5,   2, 0, 3,  2, 2);   // 20 + 5
    PP(2, 2, 5,  0, 3,   3, 2, 8,  1, 3);   // 16 + 15
    PP(3, 3, 9,  0, 3,   4, 3, 13, 1, 3);   // 16 + 15
    PP(4, 1, 11, 3, 4,   5, 4, 19, 1, 3);   // 16 + 15
    PP(4, 4, 14, 0, 3,   2, 1, 4,  1, 3);   // 16 + 15
    PP(5, 2, 17, 3, 4,   1, 0, 1,  1, 1);   // 16 + 3
    PP(5, 5, 20, 0, 3,   0, 0, 0,  0, 0);   // 16 + 1
#undef PP

    __syncthreads();
    for (int s = tid; s < 1152; s += 256) {
        int l = 0;
#pragma unroll
        for (int ll = 1; ll < 6; ll++)
            if (s >= c_FOFF[ll]) l = ll;
        int rel = s - c_FOFF[l];
        meta.out[c_OUTOFF[l] + b * 32 * (2 * l + 1) + rel] = out_s[s];
    }
}

// ---------------------------------------------------------------------------
// Host launch
// ---------------------------------------------------------------------------
extern "C" void kernel_launch(void* const* d_in, const int* in_sizes, int n_in,
                              void* d_out, int out_size) {
    Meta m;
    const int fsz[6] = {8192, 24576, 40960, 57344, 73728, 90112};
    const int wsz[6] = {49152, 81920, 106496, 114688, 114688, 98304};
    bool used[64];
    for (int i = 0; i < 64; i++) used[i] = false;
    for (int l = 0; l < 6; l++) {
        for (int idx = 0; idx < n_in; idx++) {
            if (!used[idx] && in_sizes[idx] == fsz[l]) {
                m.f[l] = (const float*)d_in[idx];
                used[idx] = true;
                break;
            }
        }
    }
    for (int l = 0; l < 6; l++) {
        for (int idx = 0; idx < n_in; idx++) {
            if (!used[idx] && in_sizes[idx] == wsz[l]) {
                m.w[l] = (const float*)d_in[idx];
                used[idx] = true;
                break;
            }
        }
    }
    m.out = (float*)d_out;

    int off = 0, g = 0, tr = 0;
    int cnt[6] = {0, 0, 0, 0, 0, 0};
    for (int l1 = 0; l1 <= 5; l1++) {
        for (int l2 = 0; l2 <= l1; l2++) {
            int lmin = l1 - l2;
            int lmax = (l1 + l2 < 5) ? (l1 + l2) : 5;
            for (int l = lmin; l <= lmax; l++) {
                m.cg_off[g][l] = off;
                m.trip_l1[tr] = l1;
                m.trip_l2[tr] = l2;
                m.trip_l[tr]  = l;
                m.trip_off[tr] = off;
                tr++;
                off += (2 * l1 + 1) * (2 * l2 + 1);
                m.col_base[g][l] = cnt[l] * 256;
                cnt[l]++;
            }
            g++;
        }
    }

    const int SMEM_BYTES = 22784 * 4;  // 91136
    cudaFuncSetAttribute(uf_kernel, cudaFuncAttributeMaxDynamicSharedMemorySize, SMEM_BYTES);

    setup_kernel<<<NTRIP + NTILE, 256>>>(m);
    uf_kernel<<<256, 256, SMEM_BYTES>>>(m);
}